// round 6
// baseline (speedup 1.0000x reference)
#include <cuda_runtime.h>
#include <cstdint>

#define DIMC 512
#define EE 336
#define E3 1008
#define NSTATE 16
#define NH 6
#define HDIM 56
#define BB 8
#define LL 4096
#define NN (BB*LL)        // 32768 tokens
#define KC 819
#define DU 64             // truncated scan kernel length
#define DK 67             // combined (scan * dconv) kernel length

// ---------------- scratch (static device memory; no allocs allowed) ----------
__device__ float g_xp[(size_t)NN*EE];
__device__ float g_qkv[(size_t)NN*E3];
__device__ float g_att[(size_t)NN*EE];
__device__ float g_imp[NN];
__device__ int   g_idx[BB*KC];
__device__ float g_ys[(size_t)BB*KC*EE];
__device__ float g_xproc[(size_t)BB*KC*DIMC];
__device__ float g_K[EE*DK];

// ============================ helpers =======================================
__device__ __forceinline__ void tf32_split(float v, uint32_t& h, uint32_t& l) {
    uint32_t hb; asm("cvt.rna.tf32.f32 %0, %1;" : "=r"(hb) : "f"(v));
    float hf = __uint_as_float(hb);
    uint32_t lb; asm("cvt.rna.tf32.f32 %0, %1;" : "=r"(lb) : "f"(v - hf));
    h = hb; l = lb;
}
__device__ __forceinline__ void mma8(float* c, const uint32_t* a, const uint32_t* b) {
    asm volatile("mma.sync.aligned.m16n8k8.row.col.f32.tf32.tf32.f32 "
        "{%0,%1,%2,%3}, {%4,%5,%6,%7}, {%8,%9}, {%0,%1,%2,%3};"
        : "+f"(c[0]), "+f"(c[1]), "+f"(c[2]), "+f"(c[3])
        : "r"(a[0]), "r"(a[1]), "r"(a[2]), "r"(a[3]), "r"(b[0]), "r"(b[1]));
}

// ================== split-tf32 (3-pass) warp-MMA GEMM =======================
// C[M,N] = op(A)[M,K] @ W[K,N] + bias.  MODE 1: DyT(tanh) on A elements.
// CTA tile 128 x BN, K-chunk 32. 8 warps (4M x 2N), warp tile 32 x BN/2.
// SMEM holds PRE-SPLIT hi/lo tf32 planes; inner loop is pure LDS + MMA.
template<int BN, int MODE>
__global__ void __launch_bounds__(256, 1) mma_gemm(
    const float* __restrict__ A, const float* __restrict__ W,
    const float* __restrict__ bias, float* __restrict__ C,
    int M, int N, int K,
    const float* __restrict__ alpha, const float* __restrict__ dw,
    const float* __restrict__ db)
{
    constexpr int PA = 36;            // A row pitch (words): conflict-free
    constexpr int PB = BN + 8;        // B row pitch: conflict-free frag LDS
    constexpr int WN = BN / 2;
    constexpr int NT8 = WN / 8;       // n8 tiles per warp (7 or 8)
    constexpr int BI = (BN * 32) / 256;

    extern __shared__ uint32_t smw[];
    uint32_t* Ah = smw;                        // [2][128*PA]
    uint32_t* Al = Ah + 2 * 128 * PA;
    uint32_t* Bh = Al + 2 * 128 * PA;          // [2][32*PB]
    uint32_t* Bl = Bh + 2 * 32 * PB;

    int tid = threadIdx.x, wid = tid >> 5, lane = tid & 31;
    int wm = (wid & 3) * 32, wn = (wid >> 2) * WN;
    int g4 = lane >> 2, t4 = lane & 3;
    int m0 = blockIdx.y * 128, n0 = blockIdx.x * BN;
    float a0s = (MODE == 1) ? __ldg(alpha) : 0.f;

    float acc[2][NT8][4];
    #pragma unroll
    for (int i = 0; i < 2; i++)
        #pragma unroll
        for (int j = 0; j < NT8; j++)
            #pragma unroll
            for (int t = 0; t < 4; t++) acc[i][j][t] = 0.f;

    int NC = (K + 31) / 32;

    uint32_t rah[4][4], ral[4][4];   // A: 4 iters x 4 values (hi/lo planes)
    uint32_t rbh[BI], rbl[BI];       // B: BI values (hi/lo planes)

    // ---- global -> regs (transform + split ONCE per element) for chunk c
    auto ldg_chunk = [&](int c) {
        int k0 = c * 32;
        #pragma unroll
        for (int it = 0; it < 4; it++) {
            int idx = tid + it * 256;
            int r = idx >> 3, f4 = idx & 7;
            int gm = m0 + r, gk = k0 + f4 * 4;
            float4 v = make_float4(0.f, 0.f, 0.f, 0.f);
            if (gm < M && gk < K) {
                v = *(const float4*)(A + (size_t)gm * K + gk);
                if (MODE == 1) {
                    float4 w4 = *(const float4*)(dw + gk);
                    float4 b4 = *(const float4*)(db + gk);
                    v.x = tanhf(a0s * v.x) * w4.x + b4.x;
                    v.y = tanhf(a0s * v.y) * w4.y + b4.y;
                    v.z = tanhf(a0s * v.z) * w4.z + b4.z;
                    v.w = tanhf(a0s * v.w) * w4.w + b4.w;
                }
            }
            tf32_split(v.x, rah[it][0], ral[it][0]);
            tf32_split(v.y, rah[it][1], ral[it][1]);
            tf32_split(v.z, rah[it][2], ral[it][2]);
            tf32_split(v.w, rah[it][3], ral[it][3]);
        }
        #pragma unroll
        for (int it = 0; it < BI; it++) {
            int idx = tid + it * 256;
            int kl = idx / BN, nr = idx - kl * BN;
            int gk = k0 + kl;
            float v = (gk < K) ? __ldg(W + (size_t)gk * N + n0 + nr) : 0.f;
            tf32_split(v, rbh[it], rbl[it]);
        }
    };
    // ---- regs -> smem planes
    auto sts_chunk = [&](int buf) {
        uint32_t* Ahb = Ah + buf * 128 * PA;
        uint32_t* Alb = Al + buf * 128 * PA;
        uint32_t* Bhb = Bh + buf * 32 * PB;
        uint32_t* Blb = Bl + buf * 32 * PB;
        #pragma unroll
        for (int it = 0; it < 4; it++) {
            int idx = tid + it * 256;
            int r = idx >> 3, f4 = idx & 7;
            int w = r * PA + f4 * 4;
            *(uint4*)(Ahb + w) = make_uint4(rah[it][0], rah[it][1], rah[it][2], rah[it][3]);
            *(uint4*)(Alb + w) = make_uint4(ral[it][0], ral[it][1], ral[it][2], ral[it][3]);
        }
        #pragma unroll
        for (int it = 0; it < BI; it++) {
            int idx = tid + it * 256;
            int kl = idx / BN, nr = idx - kl * BN;
            Bhb[kl * PB + nr] = rbh[it];
            Blb[kl * PB + nr] = rbl[it];
        }
    };
    // ---- compute one 32-wide K chunk from smem planes (pure LDS + MMA)
    auto compute = [&](int buf) {
        const uint32_t* Ahb = Ah + buf * 128 * PA;
        const uint32_t* Alb = Al + buf * 128 * PA;
        const uint32_t* Bhb = Bh + buf * 32 * PB;
        const uint32_t* Blb = Bl + buf * 32 * PB;
        #pragma unroll
        for (int kk = 0; kk < 4; kk++) {
            int k8 = kk * 8;
            uint32_t ah[2][4], al[2][4];
            #pragma unroll
            for (int mt = 0; mt < 2; mt++) {
                int r0 = (wm + mt * 16 + g4) * PA + k8 + t4;
                ah[mt][0] = Ahb[r0];
                ah[mt][1] = Ahb[r0 + 8 * PA];
                ah[mt][2] = Ahb[r0 + 4];
                ah[mt][3] = Ahb[r0 + 8 * PA + 4];
                al[mt][0] = Alb[r0];
                al[mt][1] = Alb[r0 + 8 * PA];
                al[mt][2] = Alb[r0 + 4];
                al[mt][3] = Alb[r0 + 8 * PA + 4];
            }
            uint32_t bh[NT8][2], bl[NT8][2];
            #pragma unroll
            for (int nt = 0; nt < NT8; nt++) {
                int nb = (k8 + t4) * PB + wn + nt * 8 + g4;
                bh[nt][0] = Bhb[nb];
                bh[nt][1] = Bhb[nb + 4 * PB];
                bl[nt][0] = Blb[nb];
                bl[nt][1] = Blb[nb + 4 * PB];
            }
            #pragma unroll
            for (int mt = 0; mt < 2; mt++)
                #pragma unroll
                for (int nt = 0; nt < NT8; nt++) {
                    mma8(acc[mt][nt], ah[mt], bh[nt]);
                    mma8(acc[mt][nt], ah[mt], bl[nt]);
                    mma8(acc[mt][nt], al[mt], bh[nt]);
                }
        }
    };

    ldg_chunk(0);
    sts_chunk(0);
    __syncthreads();

    for (int c = 0; c < NC; c++) {
        int p = c & 1;
        if (c + 1 < NC) ldg_chunk(c + 1);
        compute(p);
        if (c + 1 < NC) sts_chunk(p ^ 1);   // buffer p^1 fully drained last iter
        __syncthreads();
    }

    // ---- epilogue: registers -> global with bias
    #pragma unroll
    for (int mt = 0; mt < 2; mt++) {
        int gr = m0 + wm + mt * 16 + g4;
        #pragma unroll
        for (int nt = 0; nt < NT8; nt++) {
            int gc = n0 + wn + nt * 8 + t4 * 2;
            float2 bv = *(const float2*)(bias + gc);
            if (gr < M) {
                float2 o = make_float2(acc[mt][nt][0] + bv.x, acc[mt][nt][1] + bv.y);
                *(float2*)(C + (size_t)gr * N + gc) = o;
            }
            if (gr + 8 < M) {
                float2 o = make_float2(acc[mt][nt][2] + bv.x, acc[mt][nt][3] + bv.y);
                *(float2*)(C + (size_t)(gr + 8) * N + gc) = o;
            }
        }
    }
}

// ---------------- prep: combined conv kernel --------------------------------
__global__ void prep_kernel(const float* __restrict__ A, const float* __restrict__ Bp,
                            const float* __restrict__ Cp, const float* __restrict__ cw)
{
    __shared__ float U[DU][NSTATE];
    __shared__ float gk[DU];
    __shared__ float sC[NSTATE];
    int tid = threadIdx.x;
    int e = blockIdx.x;
    if (tid < 32) {
        int i = tid & 15;
        float u = 1.f / (1.f + expf(-Bp[i]));
        for (int d = 0; d < DU; d++) {
            if (tid < 16) U[d][i] = u;
            float nu = 0.f;
            #pragma unroll
            for (int j = 0; j < 16; j++)
                nu += A[i*16 + j] * __shfl_sync(0xFFFFFFFFu, u, j);
            u = nu;
        }
    }
    if (tid < 16) sC[tid] = 1.f / (1.f + expf(-Cp[e*16 + tid]));
    __syncthreads();
    for (int d = tid; d < DU; d += blockDim.x) {
        float s = 0.f;
        #pragma unroll
        for (int i = 0; i < 16; i++) s += sC[i] * U[d][i];
        gk[d] = s;
    }
    __syncthreads();
    for (int dd = tid; dd < DK; dd += blockDim.x) {
        float s = 0.f;
        #pragma unroll
        for (int d1 = 0; d1 < 4; d1++) {
            int d2 = dd - d1;
            if (d2 >= 0 && d2 < DU) s += cw[e*4 + (3 - d1)] * gk[d2];
        }
        g_K[e*DK + dd] = s;
    }
}

// ---------------- row L2-normalize ------------------------------------------
__global__ void norm_kernel(float* __restrict__ xp)
{
    int lane = threadIdx.x & 31;
    int row = blockIdx.x * 8 + (threadIdx.x >> 5);
    float* p = xp + (size_t)row * EE;
    float s = 0.f;
    for (int e = lane; e < EE; e += 32) { float v = p[e]; s += v*v; }
    #pragma unroll
    for (int o = 16; o > 0; o >>= 1) s += __shfl_xor_sync(0xFFFFFFFFu, s, o);
    float inv = 1.f / fmaxf(sqrtf(s), 1e-12f);
    for (int e = lane; e < EE; e += 32) p[e] *= inv;
}

// ---------------- attention -------------------------------------------------
__global__ void attn_kernel(const float* __restrict__ qkv,
                            float* __restrict__ att, float* __restrict__ imp)
{
    __shared__ float sq[4][E3];
    __shared__ float sc[4][36];
    __shared__ int   gb[4][NH];
    int wid = threadIdx.x >> 5, lane = threadIdx.x & 31;
    int n = blockIdx.x * 4 + wid;
    const float* row = qkv + (size_t)n * E3;
    float* s = sq[wid];
    for (int e = lane; e < E3; e += 32) s[e] = row[e];
    __syncwarp();
    for (int p = lane; p < 36; p += 32) {
        int h = p / 6, g = p - h*6;
        const float* qp = s + h*HDIM;
        const float* kp = s + EE + g*HDIM;
        float d = 0.f;
        #pragma unroll
        for (int t = 0; t < HDIM; t++) d += qp[t] * kp[t];
        sc[wid][p] = d;
    }
    __syncwarp();
    if (lane < NH) {
        float best = sc[wid][lane*6]; int bg = 0;
        #pragma unroll
        for (int g = 1; g < 6; g++) {
            float v = sc[wid][lane*6 + g];
            if (v > best) { best = v; bg = g; }   // strict > : jax tie -> lowest idx
        }
        gb[wid][lane] = bg;
    }
    __syncwarp();
    float acc = 0.f;
    for (int e = lane; e < EE; e += 32) {
        int h = e % NH, d = e / NH;
        float v = s[2*EE + gb[wid][h]*HDIM + d];
        att[(size_t)n*EE + e] = v;
        acc += v*v;
    }
    #pragma unroll
    for (int o = 16; o > 0; o >>= 1) acc += __shfl_xor_sync(0xFFFFFFFFu, acc, o);
    if (lane == 0) imp[n] = sqrtf(acc);
}

// ---------------- top-819 per batch -----------------------------------------
__global__ void topk_kernel(const float* __restrict__ imp, int* __restrict__ idxout)
{
    __shared__ unsigned long long key[LL];
    int b = blockIdx.x;
    for (int i = threadIdx.x; i < LL; i += blockDim.x) {
        unsigned fb = __float_as_uint(imp[b*LL + i]);
        key[i] = ((unsigned long long)(0xFFFFFFFFu - fb) << 32) | (unsigned)i;
    }
    __syncthreads();
    for (int k = 2; k <= LL; k <<= 1)
        for (int j = k >> 1; j > 0; j >>= 1) {
            for (int i = threadIdx.x; i < LL; i += blockDim.x) {
                int ixj = i ^ j;
                if (ixj > i) {
                    bool up = ((i & k) == 0);
                    unsigned long long a = key[i], c = key[ixj];
                    if ((a > c) == up) { key[i] = c; key[ixj] = a; }
                }
            }
            __syncthreads();
        }
    for (int i = threadIdx.x; i < KC; i += blockDim.x)
        idxout[b*KC + i] = (int)(key[i] & 0xFFFFFFFFu);
}

// ---------------- fused gather + 67-tap causal conv -------------------------
__global__ void __launch_bounds__(224) conv_kernel(const float* __restrict__ att,
                                                   const int* __restrict__ idx,
                                                   float* __restrict__ ys)
{
    const int ET = 56, JT = 64, WIN = JT + DK - 1;
    __shared__ float sp[ET][WIN + 1];
    __shared__ float Ks[ET][DK + 1];
    __shared__ int   sidx[WIN];
    int et = blockIdx.x, jt = blockIdx.y, b = blockIdx.z;
    int e0 = et * ET, j0 = jt * JT;
    int tid = threadIdx.x;

    for (int w = tid; w < WIN; w += 224) {
        int j = j0 - (DK - 1) + w;
        sidx[w] = (j >= 0 && j < KC) ? idx[b*KC + j] : -1;
    }
    for (int i = tid; i < ET*DK; i += 224) {
        int ee = i / DK, d = i - ee*DK;
        Ks[ee][d] = g_K[(e0 + ee)*DK + d];
    }
    __syncthreads();
    for (int i = tid; i < WIN*ET; i += 224) {
        int w = i / ET, ee = i - w*ET;
        int pos = sidx[w];
        sp[ee][w] = (pos >= 0) ? att[((size_t)b*LL + pos)*EE + e0 + ee] : 0.f;
    }
    __syncthreads();

    int ee = tid % ET, jg = tid / ET;
    float acc[16];
    #pragma unroll
    for (int t = 0; t < 16; t++) acc[t] = 0.f;
    int wbase = (DK - 1) + jg*16;
    for (int d = 0; d < DK; d++) {
        float kv = Ks[ee][d];
        #pragma unroll
        for (int t = 0; t < 16; t++)
            acc[t] += kv * sp[ee][wbase + t - d];
    }
    #pragma unroll
    for (int t = 0; t < 16; t++) {
        int j = j0 + jg*16 + t;
        if (j < KC) ys[((size_t)b*KC + j)*EE + e0 + ee] = acc[t];
    }
}

// ---------------- residual copy + scatter -----------------------------------
__global__ void residual_kernel(const float4* __restrict__ x, float4* __restrict__ out)
{
    size_t i = (size_t)blockIdx.x * blockDim.x + threadIdx.x;
    out[i] = x[i];
}

__global__ void scatter_kernel(const float* __restrict__ x, const float* __restrict__ xproc,
                               const int* __restrict__ idx, float* __restrict__ out)
{
    int row = blockIdx.x;
    int b = row / KC, j = row - b*KC;
    int pos = idx[b*KC + j];
    const float* xp = xproc + (size_t)row * DIMC;
    size_t base = ((size_t)b*LL + pos) * DIMC;
    for (int c = threadIdx.x; c < DIMC; c += blockDim.x)
        out[base + c] = x[base + c] + xp[c];
}

// ---------------- launch ----------------------------------------------------
extern "C" void kernel_launch(void* const* d_in, const int* in_sizes, int n_in,
                              void* d_out, int out_size)
{
    const float* x      = (const float*)d_in[0];
    const float* alpha  = (const float*)d_in[1];
    const float* dyt_w  = (const float*)d_in[2];
    const float* dyt_b  = (const float*)d_in[3];
    const float* W_in   = (const float*)d_in[4];
    const float* b_in   = (const float*)d_in[5];
    const float* W_qkv  = (const float*)d_in[6];
    const float* b_qkv  = (const float*)d_in[7];
    const float* conv_w = (const float*)d_in[8];
    const float* A      = (const float*)d_in[9];
    const float* Bp     = (const float*)d_in[10];
    const float* Cp     = (const float*)d_in[11];
    const float* W_out  = (const float*)d_in[12];
    const float* b_out  = (const float*)d_in[13];
    float* out = (float*)d_out;

    float *xp, *qkv, *att, *imp, *ys, *xproc;
    int *idx;
    cudaGetSymbolAddress((void**)&xp,    g_xp);
    cudaGetSymbolAddress((void**)&qkv,   g_qkv);
    cudaGetSymbolAddress((void**)&att,   g_att);
    cudaGetSymbolAddress((void**)&imp,   g_imp);
    cudaGetSymbolAddress((void**)&idx,   g_idx);
    cudaGetSymbolAddress((void**)&ys,    g_ys);
    cudaGetSymbolAddress((void**)&xproc, g_xproc);

    // smem words: A planes 2*2*128*36 + B planes 2*2*32*(BN+8)
    const int SMA = (4*128*36 + 4*32*(112 + 8)) * 4;   // 135168 B (BN=112)
    const int SMB = (4*128*36 + 4*32*(128 + 8)) * 4;   // 143360 B (BN=128)
    cudaFuncSetAttribute(mma_gemm<112,1>, cudaFuncAttributeMaxDynamicSharedMemorySize, SMA);
    cudaFuncSetAttribute(mma_gemm<112,0>, cudaFuncAttributeMaxDynamicSharedMemorySize, SMA);
    cudaFuncSetAttribute(mma_gemm<128,0>, cudaFuncAttributeMaxDynamicSharedMemorySize, SMB);

    // 0) scan->conv kernel precompute
    prep_kernel<<<EE, 128>>>(A, Bp, Cp, conv_w);

    // 1) xp = dyt(x) @ W_in + b_in   [32768,512]x[512,336]
    mma_gemm<112,1><<<dim3(3, NN/128), 256, SMA>>>(x, W_in, b_in, xp,
                                                   NN, EE, DIMC, alpha, dyt_w, dyt_b);

    // 2) row-normalize
    norm_kernel<<<NN/8, 256>>>(xp);

    // 3) qkv = xpn @ W_qkv + b_qkv  [32768,336]x[336,1008]
    mma_gemm<112,0><<<dim3(9, NN/128), 256, SMA>>>(xp, W_qkv, b_qkv, qkv,
                                                   NN, E3, EE, alpha, dyt_w, dyt_b);

    // 4) sparse attention (kh=1 -> argmax gather) + importance
    attn_kernel<<<NN/4, 128>>>(qkv, att, imp);

    // 5) exact sorted top-819 per batch
    topk_kernel<<<BB, 1024>>>(imp, idx);

    // 6) gather + combined dconv*scan causal convolution
    conv_kernel<<<dim3(EE/56, (KC + 63)/64, BB), 224>>>(att, idx, ys);

    // 7) xproc = ys @ W_out + b_out  [6552,336]x[336,512]
    mma_gemm<128,0><<<dim3(4, (BB*KC + 127)/128), 256, SMB>>>(ys, W_out, b_out, xproc,
                                                              BB*KC, DIMC, EE,
                                                              alpha, dyt_w, dyt_b);

    // 8) out = residual
    residual_kernel<<<(NN*DIMC/4)/1024, 1024>>>((const float4*)x, (float4*)out);

    // 9) scatter selected rows
    scatter_kernel<<<BB*KC, 128>>>(x, xproc, idx, out);
}

// round 7
// speedup vs baseline: 1.2832x; 1.2832x over previous
#include <cuda_runtime.h>
#include <cstdint>

#define DIMC 512
#define EE 336
#define E3 1008
#define NSTATE 16
#define NH 6
#define HDIM 56
#define BB 8
#define LL 4096
#define NN (BB*LL)        // 32768 tokens
#define KC 819
#define DU 64             // truncated scan kernel length
#define DK 67             // combined (scan * dconv) kernel length

// weight plane offsets (floats)
#define OFF_WIN  0
#define OFF_WQKV (512*336)
#define OFF_WOUT (512*336 + 336*1008)
#define WPL_TOTAL (512*336 + 336*1008 + 336*512)

// ---------------- scratch (static device memory; no allocs allowed) ----------
__device__ float g_xp[(size_t)NN*EE];
__device__ float g_qkv[(size_t)NN*E3];
__device__ float g_att[(size_t)NN*EE];
__device__ float g_imp[NN];
__device__ int   g_idx[BB*KC];
__device__ float g_ys[(size_t)BB*KC*EE];
__device__ float g_xproc[(size_t)BB*KC*DIMC];
__device__ float g_K[EE*DK];
__device__ float g_Wh[WPL_TOTAL];
__device__ float g_Wl[WPL_TOTAL];

// ============================ helpers =======================================
__device__ __forceinline__ uint32_t smem_u32(const void* p) {
    uint32_t a;
    asm("{ .reg .u64 t; cvta.to.shared.u64 t, %1; cvt.u32.u64 %0, t; }" : "=r"(a) : "l"(p));
    return a;
}
__device__ __forceinline__ void tf32_split(float v, uint32_t& h, uint32_t& l) {
    uint32_t hb; asm("cvt.rna.tf32.f32 %0, %1;" : "=r"(hb) : "f"(v));
    float hf = __uint_as_float(hb);
    uint32_t lb; asm("cvt.rna.tf32.f32 %0, %1;" : "=r"(lb) : "f"(v - hf));
    h = hb; l = lb;
}
__device__ __forceinline__ void mma8(float* c, const uint32_t* a, const uint32_t* b) {
    asm volatile("mma.sync.aligned.m16n8k8.row.col.f32.tf32.tf32.f32 "
        "{%0,%1,%2,%3}, {%4,%5,%6,%7}, {%8,%9}, {%0,%1,%2,%3};"
        : "+f"(c[0]), "+f"(c[1]), "+f"(c[2]), "+f"(c[3])
        : "r"(a[0]), "r"(a[1]), "r"(a[2]), "r"(a[3]), "r"(b[0]), "r"(b[1]));
}
__device__ __forceinline__ void cpa16(uint32_t dst, const void* src, uint32_t sz) {
    asm volatile("cp.async.ca.shared.global [%0], [%1], 16, %2;"
        :: "r"(dst), "l"(src), "r"(sz));
}

// ---------------- weight split: W -> hi/lo tf32 planes ----------------------
__global__ void wsplit_kernel(const float* __restrict__ W, float* __restrict__ Wh,
                              float* __restrict__ Wl, int total)
{
    int i = blockIdx.x * 256 + threadIdx.x;
    if (i < total) {
        uint32_t h, l;
        tf32_split(W[i], h, l);
        Wh[i] = __uint_as_float(h);
        Wl[i] = __uint_as_float(l);
    }
}

// ================== split-tf32 (3-pass) warp-MMA GEMM, cp.async fed =========
// C[M,N] = op(A)[M,K] @ W[K,N] + bias.  MODE 1: DyT(tanh) on A elements.
// CTA tile 128 x BN, K-chunk 32. 8 warps (4M x 2N), warp tile 32 x BN/2.
// A: cp.async raw fp32 -> smem stage -> transform to hi/lo planes.
// B: pre-split planes in global, cp.async directly to smem.
template<int BN, int MODE>
__global__ void __launch_bounds__(256, 1) mma_gemm(
    const float* __restrict__ A,
    const float* __restrict__ Wh, const float* __restrict__ Wl,
    const float* __restrict__ bias, float* __restrict__ C,
    int M, int N, int K,
    const float* __restrict__ alpha, const float* __restrict__ dw,
    const float* __restrict__ db)
{
    constexpr int PA = 36;            // A pitch (words)
    constexpr int PB = BN + 8;        // B pitch (words), conflict-free frag LDS
    constexpr int WN = BN / 2;
    constexpr int NT8 = WN / 8;
    constexpr int BQ = BN / 4;        // 16B units per B row

    extern __shared__ uint32_t smw[];
    uint32_t* rawA = smw;                      // [2][128*PA]
    uint32_t* Ah   = rawA + 2 * 128 * PA;      // [128*PA]
    uint32_t* Al   = Ah + 128 * PA;
    uint32_t* Bh   = Al + 128 * PA;            // [2][32*PB]
    uint32_t* Bl   = Bh + 2 * 32 * PB;         // [2][32*PB]

    uint32_t sbase = smem_u32(smw);
    uint32_t rawA_b = sbase;
    uint32_t Bh_b = sbase + (uint32_t)((2*128*PA + 2*128*PA) * 4);
    uint32_t Bl_b = Bh_b + (uint32_t)(2*32*PB*4);

    int tid = threadIdx.x, wid = tid >> 5, lane = tid & 31;
    int wm = (wid & 3) * 32, wn = (wid >> 2) * WN;
    int g4 = lane >> 2, t4 = lane & 3;
    int m0 = blockIdx.y * 128, n0 = blockIdx.x * BN;
    float a0s = (MODE == 1) ? __ldg(alpha) : 0.f;

    float acc[2][NT8][4];
    #pragma unroll
    for (int i = 0; i < 2; i++)
        #pragma unroll
        for (int j = 0; j < NT8; j++)
            #pragma unroll
            for (int t = 0; t < 4; t++) acc[i][j][t] = 0.f;

    int NC = (K + 31) / 32;

    // ---- async issue of chunk c (A raw + B planes)
    auto issue = [&](int c) {
        int s = c & 1;
        int k0 = c * 32;
        #pragma unroll
        for (int it = 0; it < 4; it++) {
            int idx = tid + it * 256;
            int r = idx >> 3, f4 = idx & 7;
            int gm = m0 + r, gk = k0 + f4 * 4;
            bool v = (gm < M) && (gk < K);
            const float* src = v ? (A + (size_t)gm * K + gk) : A;
            cpa16(rawA_b + (uint32_t)((s*128*PA + r*PA + f4*4) * 4), src, v ? 16u : 0u);
        }
        #pragma unroll
        for (int it = 0; it < (32*BQ + 255) / 256; it++) {
            int idx = tid + it * 256;
            if (idx < 32 * BQ) {
                int kl = idx / BQ, q = idx - kl * BQ;
                int gk = k0 + kl;
                bool v = gk < K;
                size_t go = (size_t)gk * N + n0 + q * 4;
                uint32_t so = (uint32_t)((s*32*PB + kl*PB + q*4) * 4);
                cpa16(Bh_b + so, v ? (Wh + go) : Wh, v ? 16u : 0u);
                cpa16(Bl_b + so, v ? (Wl + go) : Wl, v ? 16u : 0u);
            }
        }
        asm volatile("cp.async.commit_group;" ::: "memory");
    };

    // ---- raw A -> hi/lo planes (DyT fused for MODE 1)
    auto transform = [&](int c) {
        int s = c & 1;
        int k0 = c * 32;
        #pragma unroll
        for (int it = 0; it < 4; it++) {
            int idx = tid + it * 256;
            int r = idx >> 3, f4 = idx & 7;
            int w = r * PA + f4 * 4;
            float4 v = *(const float4*)(rawA + s * 128 * PA + w);
            if (MODE == 1) {
                int gk = k0 + f4 * 4;
                float4 w4 = *(const float4*)(dw + gk);
                float4 b4 = *(const float4*)(db + gk);
                v.x = tanhf(a0s * v.x) * w4.x + b4.x;
                v.y = tanhf(a0s * v.y) * w4.y + b4.y;
                v.z = tanhf(a0s * v.z) * w4.z + b4.z;
                v.w = tanhf(a0s * v.w) * w4.w + b4.w;
            }
            uint4 h, l;
            tf32_split(v.x, h.x, l.x);
            tf32_split(v.y, h.y, l.y);
            tf32_split(v.z, h.z, l.z);
            tf32_split(v.w, h.w, l.w);
            *(uint4*)(Ah + w) = h;
            *(uint4*)(Al + w) = l;
        }
    };

    // ---- pure LDS+MMA over one 32-wide K chunk
    auto compute = [&](int c) {
        int s = c & 1;
        const uint32_t* Bhb = Bh + s * 32 * PB;
        const uint32_t* Blb = Bl + s * 32 * PB;
        #pragma unroll
        for (int kk = 0; kk < 4; kk++) {
            int k8 = kk * 8;
            uint32_t ah[2][4], al[2][4];
            #pragma unroll
            for (int mt = 0; mt < 2; mt++) {
                int r0 = (wm + mt * 16 + g4) * PA + k8 + t4;
                ah[mt][0] = Ah[r0];
                ah[mt][1] = Ah[r0 + 8 * PA];
                ah[mt][2] = Ah[r0 + 4];
                ah[mt][3] = Ah[r0 + 8 * PA + 4];
                al[mt][0] = Al[r0];
                al[mt][1] = Al[r0 + 8 * PA];
                al[mt][2] = Al[r0 + 4];
                al[mt][3] = Al[r0 + 8 * PA + 4];
            }
            uint32_t bh[NT8][2], bl[NT8][2];
            #pragma unroll
            for (int nt = 0; nt < NT8; nt++) {
                int nb = (k8 + t4) * PB + wn + nt * 8 + g4;
                bh[nt][0] = Bhb[nb];
                bh[nt][1] = Bhb[nb + 4 * PB];
                bl[nt][0] = Blb[nb];
                bl[nt][1] = Blb[nb + 4 * PB];
            }
            #pragma unroll
            for (int mt = 0; mt < 2; mt++)
                #pragma unroll
                for (int nt = 0; nt < NT8; nt++) {
                    mma8(acc[mt][nt], ah[mt], bh[nt]);
                    mma8(acc[mt][nt], ah[mt], bl[nt]);
                    mma8(acc[mt][nt], al[mt], bh[nt]);
                }
        }
    };

    issue(0);
    for (int c = 0; c < NC; c++) {
        asm volatile("cp.async.wait_group 0;" ::: "memory");
        __syncthreads();                 // chunk c data visible; chunk c-1 fully consumed
        if (c + 1 < NC) issue(c + 1);    // overlaps transform+compute of chunk c
        transform(c);
        __syncthreads();                 // planes visible
        compute(c);
    }

    // ---- epilogue: registers -> global with bias
    #pragma unroll
    for (int mt = 0; mt < 2; mt++) {
        int gr = m0 + wm + mt * 16 + g4;
        #pragma unroll
        for (int nt = 0; nt < NT8; nt++) {
            int gc = n0 + wn + nt * 8 + t4 * 2;
            float2 bv = *(const float2*)(bias + gc);
            if (gr < M) {
                float2 o = make_float2(acc[mt][nt][0] + bv.x, acc[mt][nt][1] + bv.y);
                *(float2*)(C + (size_t)gr * N + gc) = o;
            }
            if (gr + 8 < M) {
                float2 o = make_float2(acc[mt][nt][2] + bv.x, acc[mt][nt][3] + bv.y);
                *(float2*)(C + (size_t)(gr + 8) * N + gc) = o;
            }
        }
    }
}

// ---------------- prep: combined conv kernel --------------------------------
__global__ void prep_kernel(const float* __restrict__ A, const float* __restrict__ Bp,
                            const float* __restrict__ Cp, const float* __restrict__ cw)
{
    __shared__ float U[DU][NSTATE];
    __shared__ float gk[DU];
    __shared__ float sC[NSTATE];
    int tid = threadIdx.x;
    int e = blockIdx.x;
    if (tid < 32) {
        int i = tid & 15;
        float u = 1.f / (1.f + expf(-Bp[i]));
        for (int d = 0; d < DU; d++) {
            if (tid < 16) U[d][i] = u;
            float nu = 0.f;
            #pragma unroll
            for (int j = 0; j < 16; j++)
                nu += A[i*16 + j] * __shfl_sync(0xFFFFFFFFu, u, j);
            u = nu;
        }
    }
    if (tid < 16) sC[tid] = 1.f / (1.f + expf(-Cp[e*16 + tid]));
    __syncthreads();
    for (int d = tid; d < DU; d += blockDim.x) {
        float s = 0.f;
        #pragma unroll
        for (int i = 0; i < 16; i++) s += sC[i] * U[d][i];
        gk[d] = s;
    }
    __syncthreads();
    for (int dd = tid; dd < DK; dd += blockDim.x) {
        float s = 0.f;
        #pragma unroll
        for (int d1 = 0; d1 < 4; d1++) {
            int d2 = dd - d1;
            if (d2 >= 0 && d2 < DU) s += cw[e*4 + (3 - d1)] * gk[d2];
        }
        g_K[e*DK + dd] = s;
    }
}

// ---------------- row L2-normalize ------------------------------------------
__global__ void norm_kernel(float* __restrict__ xp)
{
    int lane = threadIdx.x & 31;
    int row = blockIdx.x * 8 + (threadIdx.x >> 5);
    float* p = xp + (size_t)row * EE;
    float s = 0.f;
    for (int e = lane; e < EE; e += 32) { float v = p[e]; s += v*v; }
    #pragma unroll
    for (int o = 16; o > 0; o >>= 1) s += __shfl_xor_sync(0xFFFFFFFFu, s, o);
    float inv = 1.f / fmaxf(sqrtf(s), 1e-12f);
    for (int e = lane; e < EE; e += 32) p[e] *= inv;
}

// ---------------- attention -------------------------------------------------
__global__ void attn_kernel(const float* __restrict__ qkv,
                            float* __restrict__ att, float* __restrict__ imp)
{
    __shared__ float sq[4][E3];
    __shared__ float sc[4][36];
    __shared__ int   gb[4][NH];
    int wid = threadIdx.x >> 5, lane = threadIdx.x & 31;
    int n = blockIdx.x * 4 + wid;
    const float* row = qkv + (size_t)n * E3;
    float* s = sq[wid];
    for (int e = lane; e < E3; e += 32) s[e] = row[e];
    __syncwarp();
    for (int p = lane; p < 36; p += 32) {
        int h = p / 6, g = p - h*6;
        const float* qp = s + h*HDIM;
        const float* kp = s + EE + g*HDIM;
        float d = 0.f;
        #pragma unroll
        for (int t = 0; t < HDIM; t++) d += qp[t] * kp[t];
        sc[wid][p] = d;
    }
    __syncwarp();
    if (lane < NH) {
        float best = sc[wid][lane*6]; int bg = 0;
        #pragma unroll
        for (int g = 1; g < 6; g++) {
            float v = sc[wid][lane*6 + g];
            if (v > best) { best = v; bg = g; }   // strict > : jax tie -> lowest idx
        }
        gb[wid][lane] = bg;
    }
    __syncwarp();
    float acc = 0.f;
    for (int e = lane; e < EE; e += 32) {
        int h = e % NH, d = e / NH;
        float v = s[2*EE + gb[wid][h]*HDIM + d];
        att[(size_t)n*EE + e] = v;
        acc += v*v;
    }
    #pragma unroll
    for (int o = 16; o > 0; o >>= 1) acc += __shfl_xor_sync(0xFFFFFFFFu, acc, o);
    if (lane == 0) imp[n] = sqrtf(acc);
}

// ---------------- top-819 per batch -----------------------------------------
__global__ void topk_kernel(const float* __restrict__ imp, int* __restrict__ idxout)
{
    __shared__ unsigned long long key[LL];
    int b = blockIdx.x;
    for (int i = threadIdx.x; i < LL; i += blockDim.x) {
        unsigned fb = __float_as_uint(imp[b*LL + i]);
        key[i] = ((unsigned long long)(0xFFFFFFFFu - fb) << 32) | (unsigned)i;
    }
    __syncthreads();
    for (int k = 2; k <= LL; k <<= 1)
        for (int j = k >> 1; j > 0; j >>= 1) {
            for (int i = threadIdx.x; i < LL; i += blockDim.x) {
                int ixj = i ^ j;
                if (ixj > i) {
                    bool up = ((i & k) == 0);
                    unsigned long long a = key[i], c = key[ixj];
                    if ((a > c) == up) { key[i] = c; key[ixj] = a; }
                }
            }
            __syncthreads();
        }
    for (int i = threadIdx.x; i < KC; i += blockDim.x)
        idxout[b*KC + i] = (int)(key[i] & 0xFFFFFFFFu);
}

// ---------------- fused gather + 67-tap causal conv -------------------------
__global__ void __launch_bounds__(224) conv_kernel(const float* __restrict__ att,
                                                   const int* __restrict__ idx,
                                                   float* __restrict__ ys)
{
    const int ET = 56, JT = 64, WIN = JT + DK - 1;
    __shared__ float sp[ET][WIN + 1];
    __shared__ float Ks[ET][DK + 1];
    __shared__ int   sidx[WIN];
    int et = blockIdx.x, jt = blockIdx.y, b = blockIdx.z;
    int e0 = et * ET, j0 = jt * JT;
    int tid = threadIdx.x;

    for (int w = tid; w < WIN; w += 224) {
        int j = j0 - (DK - 1) + w;
        sidx[w] = (j >= 0 && j < KC) ? idx[b*KC + j] : -1;
    }
    for (int i = tid; i < ET*DK; i += 224) {
        int ee = i / DK, d = i - ee*DK;
        Ks[ee][d] = g_K[(e0 + ee)*DK + d];
    }
    __syncthreads();
    for (int i = tid; i < WIN*ET; i += 224) {
        int w = i / ET, ee = i - w*ET;
        int pos = sidx[w];
        sp[ee][w] = (pos >= 0) ? att[((size_t)b*LL + pos)*EE + e0 + ee] : 0.f;
    }
    __syncthreads();

    int ee = tid % ET, jg = tid / ET;
    float acc[16];
    #pragma unroll
    for (int t = 0; t < 16; t++) acc[t] = 0.f;
    int wbase = (DK - 1) + jg*16;
    for (int d = 0; d < DK; d++) {
        float kv = Ks[ee][d];
        #pragma unroll
        for (int t = 0; t < 16; t++)
            acc[t] += kv * sp[ee][wbase + t - d];
    }
    #pragma unroll
    for (int t = 0; t < 16; t++) {
        int j = j0 + jg*16 + t;
        if (j < KC) ys[((size_t)b*KC + j)*EE + e0 + ee] = acc[t];
    }
}

// ---------------- residual copy + scatter -----------------------------------
__global__ void residual_kernel(const float4* __restrict__ x, float4* __restrict__ out)
{
    size_t i = (size_t)blockIdx.x * blockDim.x + threadIdx.x;
    out[i] = x[i];
}

__global__ void scatter_kernel(const float* __restrict__ x, const float* __restrict__ xproc,
                               const int* __restrict__ idx, float* __restrict__ out)
{
    int row = blockIdx.x;
    int b = row / KC, j = row - b*KC;
    int pos = idx[b*KC + j];
    const float* xp = xproc + (size_t)row * DIMC;
    size_t base = ((size_t)b*LL + pos) * DIMC;
    for (int c = threadIdx.x; c < DIMC; c += blockDim.x)
        out[base + c] = x[base + c] + xp[c];
}

// ---------------- launch ----------------------------------------------------
extern "C" void kernel_launch(void* const* d_in, const int* in_sizes, int n_in,
                              void* d_out, int out_size)
{
    const float* x      = (const float*)d_in[0];
    const float* alpha  = (const float*)d_in[1];
    const float* dyt_w  = (const float*)d_in[2];
    const float* dyt_b  = (const float*)d_in[3];
    const float* W_in   = (const float*)d_in[4];
    const float* b_in   = (const float*)d_in[5];
    const float* W_qkv  = (const float*)d_in[6];
    const float* b_qkv  = (const float*)d_in[7];
    const float* conv_w = (const float*)d_in[8];
    const float* A      = (const float*)d_in[9];
    const float* Bp     = (const float*)d_in[10];
    const float* Cp     = (const float*)d_in[11];
    const float* W_out  = (const float*)d_in[12];
    const float* b_out  = (const float*)d_in[13];
    float* out = (float*)d_out;

    float *xp, *qkv, *att, *imp, *ys, *xproc, *wh, *wl;
    int *idx;
    cudaGetSymbolAddress((void**)&xp,    g_xp);
    cudaGetSymbolAddress((void**)&qkv,   g_qkv);
    cudaGetSymbolAddress((void**)&att,   g_att);
    cudaGetSymbolAddress((void**)&imp,   g_imp);
    cudaGetSymbolAddress((void**)&idx,   g_idx);
    cudaGetSymbolAddress((void**)&ys,    g_ys);
    cudaGetSymbolAddress((void**)&xproc, g_xproc);
    cudaGetSymbolAddress((void**)&wh,    g_Wh);
    cudaGetSymbolAddress((void**)&wl,    g_Wl);

    // smem words: rawA 2*128*36 + planes 2*128*36 + B 2*2*32*(BN+8)
    const int SMA = (2*128*36 + 2*128*36 + 4*32*(112 + 8)) * 4;   // 135168 B
    const int SMB = (2*128*36 + 2*128*36 + 4*32*(128 + 8)) * 4;   // 143360 B
    cudaFuncSetAttribute(mma_gemm<112,1>, cudaFuncAttributeMaxDynamicSharedMemorySize, SMA);
    cudaFuncSetAttribute(mma_gemm<112,0>, cudaFuncAttributeMaxDynamicSharedMemorySize, SMA);
    cudaFuncSetAttribute(mma_gemm<128,0>, cudaFuncAttributeMaxDynamicSharedMemorySize, SMB);

    // 0) weight plane split (one-time cheap) + scan->conv kernel precompute
    wsplit_kernel<<<(512*336 + 255)/256, 256>>>(W_in,  wh + OFF_WIN,  wl + OFF_WIN,  512*336);
    wsplit_kernel<<<(336*1008 + 255)/256, 256>>>(W_qkv, wh + OFF_WQKV, wl + OFF_WQKV, 336*1008);
    wsplit_kernel<<<(336*512 + 255)/256, 256>>>(W_out, wh + OFF_WOUT, wl + OFF_WOUT, 336*512);
    prep_kernel<<<EE, 128>>>(A, Bp, Cp, conv_w);

    // 1) xp = dyt(x) @ W_in + b_in   [32768,512]x[512,336]
    mma_gemm<112,1><<<dim3(3, NN/128), 256, SMA>>>(x, wh + OFF_WIN, wl + OFF_WIN,
                                                   b_in, xp, NN, EE, DIMC,
                                                   alpha, dyt_w, dyt_b);

    // 2) row-normalize
    norm_kernel<<<NN/8, 256>>>(xp);

    // 3) qkv = xpn @ W_qkv + b_qkv  [32768,336]x[336,1008]
    mma_gemm<112,0><<<dim3(9, NN/128), 256, SMA>>>(xp, wh + OFF_WQKV, wl + OFF_WQKV,
                                                   b_qkv, qkv, NN, E3, EE,
                                                   alpha, dyt_w, dyt_b);

    // 4) sparse attention (kh=1 -> argmax gather) + importance
    attn_kernel<<<NN/4, 128>>>(qkv, att, imp);

    // 5) exact sorted top-819 per batch
    topk_kernel<<<BB, 1024>>>(imp, idx);

    // 6) gather + combined dconv*scan causal convolution
    conv_kernel<<<dim3(EE/56, (KC + 63)/64, BB), 224>>>(att, idx, ys);

    // 7) xproc = ys @ W_out + b_out  [6552,336]x[336,512]
    mma_gemm<128,0><<<dim3(4, (BB*KC + 127)/128), 256, SMB>>>(ys, wh + OFF_WOUT, wl + OFF_WOUT,
                                                              b_out, xproc, BB*KC, DIMC, EE,
                                                              alpha, dyt_w, dyt_b);

    // 8) out = residual
    residual_kernel<<<(NN*DIMC/4)/1024, 1024>>>((const float4*)x, (float4*)out);

    // 9) scatter selected rows
    scatter_kernel<<<BB*KC, 128>>>(x, xproc, idx, out);
}

// round 8
// speedup vs baseline: 1.2902x; 1.0054x over previous
#include <cuda_runtime.h>
#include <cstdint>

#define DIMC 512
#define EE 336
#define E3 1008
#define NSTATE 16
#define NH 6
#define HDIM 56
#define BB 8
#define LL 4096
#define NN (BB*LL)        // 32768 tokens
#define KC 819
#define DU 64             // truncated scan kernel length
#define DK 67             // combined (scan * dconv) kernel length

// weight plane offsets (floats)
#define OFF_WIN  0
#define OFF_WQKV (512*336)
#define OFF_WOUT (512*336 + 336*1008)
#define WPL_TOTAL (512*336 + 336*1008 + 336*512)

// ---------------- scratch (static device memory; no allocs allowed) ----------
__device__ float g_xp[(size_t)NN*EE];
__device__ float g_qkv[(size_t)NN*E3];
__device__ float g_att[(size_t)NN*EE];
__device__ float g_imp[NN];
__device__ int   g_idx[BB*KC];
__device__ float g_xproc[(size_t)BB*KC*DIMC];
__device__ float g_K[EE*DK];
__device__ float g_Wh[WPL_TOTAL];
__device__ float g_Wl[WPL_TOTAL];
__device__ float g_xph[(size_t)NN*EE];     // xpn hi plane
__device__ float g_xpl[(size_t)NN*EE];     // xpn lo plane
__device__ float g_ysh[(size_t)BB*KC*EE];  // ys hi plane
__device__ float g_ysl[(size_t)BB*KC*EE];  // ys lo plane

// ============================ helpers =======================================
__device__ __forceinline__ uint32_t smem_u32(const void* p) {
    uint32_t a;
    asm("{ .reg .u64 t; cvta.to.shared.u64 t, %1; cvt.u32.u64 %0, t; }" : "=r"(a) : "l"(p));
    return a;
}
__device__ __forceinline__ void tf32_split(float v, uint32_t& h, uint32_t& l) {
    uint32_t hb; asm("cvt.rna.tf32.f32 %0, %1;" : "=r"(hb) : "f"(v));
    float hf = __uint_as_float(hb);
    uint32_t lb; asm("cvt.rna.tf32.f32 %0, %1;" : "=r"(lb) : "f"(v - hf));
    h = hb; l = lb;
}
__device__ __forceinline__ void mma8(float* c, const uint32_t* a, const uint32_t* b) {
    asm volatile("mma.sync.aligned.m16n8k8.row.col.f32.tf32.tf32.f32 "
        "{%0,%1,%2,%3}, {%4,%5,%6,%7}, {%8,%9}, {%0,%1,%2,%3};"
        : "+f"(c[0]), "+f"(c[1]), "+f"(c[2]), "+f"(c[3])
        : "r"(a[0]), "r"(a[1]), "r"(a[2]), "r"(a[3]), "r"(b[0]), "r"(b[1]));
}
__device__ __forceinline__ void cpa16(uint32_t dst, const void* src, uint32_t sz) {
    asm volatile("cp.async.ca.shared.global [%0], [%1], 16, %2;"
        :: "r"(dst), "l"(src), "r"(sz));
}

// ---------------- weight split: W -> hi/lo tf32 planes ----------------------
__global__ void wsplit_kernel(const float* __restrict__ W, float* __restrict__ Wh,
                              float* __restrict__ Wl, int total)
{
    int i = blockIdx.x * 256 + threadIdx.x;
    if (i < total) {
        uint32_t h, l;
        tf32_split(W[i], h, l);
        Wh[i] = __uint_as_float(h);
        Wl[i] = __uint_as_float(l);
    }
}

// ================== split-tf32 (3-pass) warp-MMA GEMM, cp.async fed =========
// C[M,N] = op(A)[M,K] @ W[K,N] + bias.
// MODE 1: A raw fp32 streamed to smem, DyT(tanh)+split transform in-kernel.
// MODE 0: A pre-split hi/lo planes streamed directly -> no transform phase.
// CTA tile 128 x BN, K-chunk 32. 8 warps (4M x 2N), warp tile 32 x BN/2.
template<int BN, int MODE>
__global__ void __launch_bounds__(256, 1) mma_gemm(
    const float* __restrict__ A,
    const float* __restrict__ Ahg, const float* __restrict__ Alg,
    const float* __restrict__ Wh, const float* __restrict__ Wl,
    const float* __restrict__ bias, float* __restrict__ C,
    int M, int N, int K,
    const float* __restrict__ alpha, const float* __restrict__ dw,
    const float* __restrict__ db)
{
    constexpr int PA = 36;            // A pitch (words), conflict-free frag LDS
    constexpr int PB = BN + 8;        // B pitch (words), conflict-free frag LDS
    constexpr int WN = BN / 2;
    constexpr int NT8 = WN / 8;
    constexpr int BQ = BN / 4;        // 16B units per B row
    constexpr int AST = (MODE == 0) ? 2 : 1;   // plane buffer stages

    extern __shared__ uint32_t smw[];
    uint32_t* rawA = smw;                                       // MODE1 only: [2][128*PA]
    uint32_t* AhP  = smw + ((MODE == 1) ? 2 * 128 * PA : 0);    // [AST][128*PA]
    uint32_t* AlP  = AhP + AST * 128 * PA;
    uint32_t* BhP  = AlP + AST * 128 * PA;                      // [2][32*PB]
    uint32_t* BlP  = BhP + 2 * 32 * PB;

    uint32_t sbase  = smem_u32(smw);
    uint32_t rawA_b = sbase;
    uint32_t AhP_b  = sbase + (uint32_t)(((MODE == 1) ? 2*128*PA : 0) * 4);
    uint32_t AlP_b  = AhP_b + (uint32_t)(AST * 128 * PA * 4);
    uint32_t BhP_b  = AlP_b + (uint32_t)(AST * 128 * PA * 4);
    uint32_t BlP_b  = BhP_b + (uint32_t)(2 * 32 * PB * 4);

    int tid = threadIdx.x, wid = tid >> 5, lane = tid & 31;
    int wm = (wid & 3) * 32, wn = (wid >> 2) * WN;
    int g4 = lane >> 2, t4 = lane & 3;
    int m0 = blockIdx.y * 128, n0 = blockIdx.x * BN;
    float a0s = (MODE == 1) ? __ldg(alpha) : 0.f;

    float acc[2][NT8][4];
    #pragma unroll
    for (int i = 0; i < 2; i++)
        #pragma unroll
        for (int j = 0; j < NT8; j++)
            #pragma unroll
            for (int t = 0; t < 4; t++) acc[i][j][t] = 0.f;

    int NC = (K + 31) / 32;

    // ---- async issue of chunk c
    auto issue = [&](int c) {
        int s = c & 1;
        int k0 = c * 32;
        #pragma unroll
        for (int it = 0; it < 4; it++) {
            int idx = tid + it * 256;
            int r = idx >> 3, f4 = idx & 7;
            int gm = m0 + r, gk = k0 + f4 * 4;
            bool v = (gm < M) && (gk < K);
            size_t go = (size_t)gm * K + gk;
            if (MODE == 1) {
                cpa16(rawA_b + (uint32_t)((s*128*PA + r*PA + f4*4) * 4),
                      v ? (A + go) : A, v ? 16u : 0u);
            } else {
                uint32_t so = (uint32_t)((s*128*PA + r*PA + f4*4) * 4);
                cpa16(AhP_b + so, v ? (Ahg + go) : Ahg, v ? 16u : 0u);
                cpa16(AlP_b + so, v ? (Alg + go) : Alg, v ? 16u : 0u);
            }
        }
        #pragma unroll
        for (int it = 0; it < (32*BQ + 255) / 256; it++) {
            int idx = tid + it * 256;
            if (idx < 32 * BQ) {
                int kl = idx / BQ, q = idx - kl * BQ;
                int gk = k0 + kl;
                bool v = gk < K;
                size_t go = (size_t)gk * N + n0 + q * 4;
                uint32_t so = (uint32_t)((s*32*PB + kl*PB + q*4) * 4);
                cpa16(BhP_b + so, v ? (Wh + go) : Wh, v ? 16u : 0u);
                cpa16(BlP_b + so, v ? (Wl + go) : Wl, v ? 16u : 0u);
            }
        }
        asm volatile("cp.async.commit_group;" ::: "memory");
    };

    // ---- MODE1 only: raw A -> hi/lo planes with DyT fused
    auto transform = [&](int c) {
        int s = c & 1;
        int k0 = c * 32;
        #pragma unroll
        for (int it = 0; it < 4; it++) {
            int idx = tid + it * 256;
            int r = idx >> 3, f4 = idx & 7;
            int w = r * PA + f4 * 4;
            float4 v = *(const float4*)(rawA + s * 128 * PA + w);
            int gk = k0 + f4 * 4;
            float4 w4 = *(const float4*)(dw + gk);
            float4 b4 = *(const float4*)(db + gk);
            v.x = tanhf(a0s * v.x) * w4.x + b4.x;
            v.y = tanhf(a0s * v.y) * w4.y + b4.y;
            v.z = tanhf(a0s * v.z) * w4.z + b4.z;
            v.w = tanhf(a0s * v.w) * w4.w + b4.w;
            uint4 h, l;
            tf32_split(v.x, h.x, l.x);
            tf32_split(v.y, h.y, l.y);
            tf32_split(v.z, h.z, l.z);
            tf32_split(v.w, h.w, l.w);
            *(uint4*)(AhP + w) = h;
            *(uint4*)(AlP + w) = l;
        }
    };

    // ---- pure LDS+MMA over one 32-wide K chunk
    auto compute = [&](int c) {
        int s = c & 1;
        const uint32_t* Ahb = AhP + ((MODE == 0) ? s * 128 * PA : 0);
        const uint32_t* Alb = AlP + ((MODE == 0) ? s * 128 * PA : 0);
        const uint32_t* Bhb = BhP + s * 32 * PB;
        const uint32_t* Blb = BlP + s * 32 * PB;
        #pragma unroll
        for (int kk = 0; kk < 4; kk++) {
            int k8 = kk * 8;
            uint32_t ah[2][4], al[2][4];
            #pragma unroll
            for (int mt = 0; mt < 2; mt++) {
                int r0 = (wm + mt * 16 + g4) * PA + k8 + t4;
                ah[mt][0] = Ahb[r0];
                ah[mt][1] = Ahb[r0 + 8 * PA];
                ah[mt][2] = Ahb[r0 + 4];
                ah[mt][3] = Ahb[r0 + 8 * PA + 4];
                al[mt][0] = Alb[r0];
                al[mt][1] = Alb[r0 + 8 * PA];
                al[mt][2] = Alb[r0 + 4];
                al[mt][3] = Alb[r0 + 8 * PA + 4];
            }
            uint32_t bh[NT8][2], bl[NT8][2];
            #pragma unroll
            for (int nt = 0; nt < NT8; nt++) {
                int nb = (k8 + t4) * PB + wn + nt * 8 + g4;
                bh[nt][0] = Bhb[nb];
                bh[nt][1] = Bhb[nb + 4 * PB];
                bl[nt][0] = Blb[nb];
                bl[nt][1] = Blb[nb + 4 * PB];
            }
            #pragma unroll
            for (int mt = 0; mt < 2; mt++)
                #pragma unroll
                for (int nt = 0; nt < NT8; nt++) {
                    mma8(acc[mt][nt], ah[mt], bh[nt]);
                    mma8(acc[mt][nt], ah[mt], bl[nt]);
                    mma8(acc[mt][nt], al[mt], bh[nt]);
                }
        }
    };

    issue(0);
    for (int c = 0; c < NC; c++) {
        asm volatile("cp.async.wait_group 0;" ::: "memory");
        __syncthreads();                 // chunk c visible; prev stage fully consumed
        if (c + 1 < NC) issue(c + 1);    // overlaps compute (and transform) of chunk c
        if (MODE == 1) {
            transform(c);
            __syncthreads();             // planes visible
        }
        compute(c);
    }

    // ---- epilogue: registers -> global with bias
    #pragma unroll
    for (int mt = 0; mt < 2; mt++) {
        int gr = m0 + wm + mt * 16 + g4;
        #pragma unroll
        for (int nt = 0; nt < NT8; nt++) {
            int gc = n0 + wn + nt * 8 + t4 * 2;
            float2 bv = *(const float2*)(bias + gc);
            if (gr < M) {
                float2 o = make_float2(acc[mt][nt][0] + bv.x, acc[mt][nt][1] + bv.y);
                *(float2*)(C + (size_t)gr * N + gc) = o;
            }
            if (gr + 8 < M) {
                float2 o = make_float2(acc[mt][nt][2] + bv.x, acc[mt][nt][3] + bv.y);
                *(float2*)(C + (size_t)(gr + 8) * N + gc) = o;
            }
        }
    }
}

// ---------------- prep: combined conv kernel --------------------------------
__global__ void prep_kernel(const float* __restrict__ A, const float* __restrict__ Bp,
                            const float* __restrict__ Cp, const float* __restrict__ cw)
{
    __shared__ float U[DU][NSTATE];
    __shared__ float gk[DU];
    __shared__ float sC[NSTATE];
    int tid = threadIdx.x;
    int e = blockIdx.x;
    if (tid < 32) {
        int i = tid & 15;
        float u = 1.f / (1.f + expf(-Bp[i]));
        for (int d = 0; d < DU; d++) {
            if (tid < 16) U[d][i] = u;
            float nu = 0.f;
            #pragma unroll
            for (int j = 0; j < 16; j++)
                nu += A[i*16 + j] * __shfl_sync(0xFFFFFFFFu, u, j);
            u = nu;
        }
    }
    if (tid < 16) sC[tid] = 1.f / (1.f + expf(-Cp[e*16 + tid]));
    __syncthreads();
    for (int d = tid; d < DU; d += blockDim.x) {
        float s = 0.f;
        #pragma unroll
        for (int i = 0; i < 16; i++) s += sC[i] * U[d][i];
        gk[d] = s;
    }
    __syncthreads();
    for (int dd = tid; dd < DK; dd += blockDim.x) {
        float s = 0.f;
        #pragma unroll
        for (int d1 = 0; d1 < 4; d1++) {
            int d2 = dd - d1;
            if (d2 >= 0 && d2 < DU) s += cw[e*4 + (3 - d1)] * gk[d2];
        }
        g_K[e*DK + dd] = s;
    }
}

// ---------------- row L2-normalize -> pre-split hi/lo planes ----------------
__global__ void norm_kernel(const float* __restrict__ xp,
                            float* __restrict__ xh, float* __restrict__ xl)
{
    int lane = threadIdx.x & 31;
    int row = blockIdx.x * 8 + (threadIdx.x >> 5);
    const float* p = xp + (size_t)row * EE;
    float s = 0.f;
    for (int e = lane; e < EE; e += 32) { float v = p[e]; s += v*v; }
    #pragma unroll
    for (int o = 16; o > 0; o >>= 1) s += __shfl_xor_sync(0xFFFFFFFFu, s, o);
    float inv = 1.f / fmaxf(sqrtf(s), 1e-12f);
    for (int e = lane; e < EE; e += 32) {
        float v = p[e] * inv;
        uint32_t h, l;
        tf32_split(v, h, l);
        xh[(size_t)row * EE + e] = __uint_as_float(h);
        xl[(size_t)row * EE + e] = __uint_as_float(l);
    }
}

// ---------------- attention -------------------------------------------------
__global__ void attn_kernel(const float* __restrict__ qkv,
                            float* __restrict__ att, float* __restrict__ imp)
{
    __shared__ float sq[4][E3];
    __shared__ float sc[4][36];
    __shared__ int   gb[4][NH];
    int wid = threadIdx.x >> 5, lane = threadIdx.x & 31;
    int n = blockIdx.x * 4 + wid;
    const float* row = qkv + (size_t)n * E3;
    float* s = sq[wid];
    for (int e = lane; e < E3; e += 32) s[e] = row[e];
    __syncwarp();
    for (int p = lane; p < 36; p += 32) {
        int h = p / 6, g = p - h*6;
        const float* qp = s + h*HDIM;
        const float* kp = s + EE + g*HDIM;
        float d = 0.f;
        #pragma unroll
        for (int t = 0; t < HDIM; t++) d += qp[t] * kp[t];
        sc[wid][p] = d;
    }
    __syncwarp();
    if (lane < NH) {
        float best = sc[wid][lane*6]; int bg = 0;
        #pragma unroll
        for (int g = 1; g < 6; g++) {
            float v = sc[wid][lane*6 + g];
            if (v > best) { best = v; bg = g; }   // strict > : jax tie -> lowest idx
        }
        gb[wid][lane] = bg;
    }
    __syncwarp();
    float acc = 0.f;
    for (int e = lane; e < EE; e += 32) {
        int h = e % NH, d = e / NH;
        float v = s[2*EE + gb[wid][h]*HDIM + d];
        att[(size_t)n*EE + e] = v;
        acc += v*v;
    }
    #pragma unroll
    for (int o = 16; o > 0; o >>= 1) acc += __shfl_xor_sync(0xFFFFFFFFu, acc, o);
    if (lane == 0) imp[n] = sqrtf(acc);
}

// ---------------- top-819 per batch -----------------------------------------
__global__ void topk_kernel(const float* __restrict__ imp, int* __restrict__ idxout)
{
    __shared__ unsigned long long key[LL];
    int b = blockIdx.x;
    for (int i = threadIdx.x; i < LL; i += blockDim.x) {
        unsigned fb = __float_as_uint(imp[b*LL + i]);
        key[i] = ((unsigned long long)(0xFFFFFFFFu - fb) << 32) | (unsigned)i;
    }
    __syncthreads();
    for (int k = 2; k <= LL; k <<= 1)
        for (int j = k >> 1; j > 0; j >>= 1) {
            for (int i = threadIdx.x; i < LL; i += blockDim.x) {
                int ixj = i ^ j;
                if (ixj > i) {
                    bool up = ((i & k) == 0);
                    unsigned long long a = key[i], c = key[ixj];
                    if ((a > c) == up) { key[i] = c; key[ixj] = a; }
                }
            }
            __syncthreads();
        }
    for (int i = threadIdx.x; i < KC; i += blockDim.x)
        idxout[b*KC + i] = (int)(key[i] & 0xFFFFFFFFu);
}

// ---------------- fused gather + 67-tap causal conv -> ys planes ------------
__global__ void __launch_bounds__(224) conv_kernel(const float* __restrict__ att,
                                                   const int* __restrict__ idx,
                                                   float* __restrict__ ysh,
                                                   float* __restrict__ ysl)
{
    const int ET = 56, JT = 64, WIN = JT + DK - 1;
    __shared__ float sp[ET][WIN + 1];
    __shared__ float Ks[ET][DK + 1];
    __shared__ int   sidx[WIN];
    int et = blockIdx.x, jt = blockIdx.y, b = blockIdx.z;
    int e0 = et * ET, j0 = jt * JT;
    int tid = threadIdx.x;

    for (int w = tid; w < WIN; w += 224) {
        int j = j0 - (DK - 1) + w;
        sidx[w] = (j >= 0 && j < KC) ? idx[b*KC + j] : -1;
    }
    for (int i = tid; i < ET*DK; i += 224) {
        int ee = i / DK, d = i - ee*DK;
        Ks[ee][d] = g_K[(e0 + ee)*DK + d];
    }
    __syncthreads();
    for (int i = tid; i < WIN*ET; i += 224) {
        int w = i / ET, ee = i - w*ET;
        int pos = sidx[w];
        sp[ee][w] = (pos >= 0) ? att[((size_t)b*LL + pos)*EE + e0 + ee] : 0.f;
    }
    __syncthreads();

    int ee = tid % ET, jg = tid / ET;
    float acc[16];
    #pragma unroll
    for (int t = 0; t < 16; t++) acc[t] = 0.f;
    int wbase = (DK - 1) + jg*16;
    for (int d = 0; d < DK; d++) {
        float kv = Ks[ee][d];
        #pragma unroll
        for (int t = 0; t < 16; t++)
            acc[t] += kv * sp[ee][wbase + t - d];
    }
    #pragma unroll
    for (int t = 0; t < 16; t++) {
        int j = j0 + jg*16 + t;
        if (j < KC) {
            uint32_t h, l;
            tf32_split(acc[t], h, l);
            size_t o = ((size_t)b*KC + j)*EE + e0 + ee;
            ysh[o] = __uint_as_float(h);
            ysl[o] = __uint_as_float(l);
        }
    }
}

// ---------------- residual copy + scatter -----------------------------------
__global__ void residual_kernel(const float4* __restrict__ x, float4* __restrict__ out)
{
    size_t i = (size_t)blockIdx.x * blockDim.x + threadIdx.x;
    out[i] = x[i];
}

__global__ void scatter_kernel(const float* __restrict__ x, const float* __restrict__ xproc,
                               const int* __restrict__ idx, float* __restrict__ out)
{
    int row = blockIdx.x;
    int b = row / KC, j = row - b*KC;
    int pos = idx[b*KC + j];
    const float* xp = xproc + (size_t)row * DIMC;
    size_t base = ((size_t)b*LL + pos) * DIMC;
    for (int c = threadIdx.x; c < DIMC; c += blockDim.x)
        out[base + c] = x[base + c] + xp[c];
}

// ---------------- launch ----------------------------------------------------
extern "C" void kernel_launch(void* const* d_in, const int* in_sizes, int n_in,
                              void* d_out, int out_size)
{
    const float* x      = (const float*)d_in[0];
    const float* alpha  = (const float*)d_in[1];
    const float* dyt_w  = (const float*)d_in[2];
    const float* dyt_b  = (const float*)d_in[3];
    const float* W_in   = (const float*)d_in[4];
    const float* b_in   = (const float*)d_in[5];
    const float* W_qkv  = (const float*)d_in[6];
    const float* b_qkv  = (const float*)d_in[7];
    const float* conv_w = (const float*)d_in[8];
    const float* A      = (const float*)d_in[9];
    const float* Bp     = (const float*)d_in[10];
    const float* Cp     = (const float*)d_in[11];
    const float* W_out  = (const float*)d_in[12];
    const float* b_out  = (const float*)d_in[13];
    float* out = (float*)d_out;

    float *xp, *qkv, *att, *imp, *xproc, *wh, *wl, *xph, *xpl, *ysh, *ysl;
    int *idx;
    cudaGetSymbolAddress((void**)&xp,    g_xp);
    cudaGetSymbolAddress((void**)&qkv,   g_qkv);
    cudaGetSymbolAddress((void**)&att,   g_att);
    cudaGetSymbolAddress((void**)&imp,   g_imp);
    cudaGetSymbolAddress((void**)&idx,   g_idx);
    cudaGetSymbolAddress((void**)&xproc, g_xproc);
    cudaGetSymbolAddress((void**)&wh,    g_Wh);
    cudaGetSymbolAddress((void**)&wl,    g_Wl);
    cudaGetSymbolAddress((void**)&xph,   g_xph);
    cudaGetSymbolAddress((void**)&xpl,   g_xpl);
    cudaGetSymbolAddress((void**)&ysh,   g_ysh);
    cudaGetSymbolAddress((void**)&ysl,   g_ysl);

    // smem: MODE1 = rawA(2) + planes(1) + B(2x2); MODE0 = planes(2x2) + B(2x2)
    const int SM_M1  = (2*128*36 + 2*128*36 + 4*32*(112 + 8)) * 4;  // 135168
    const int SM_M0A = (4*128*36 + 4*32*(112 + 8)) * 4;             // 135168
    const int SM_M0B = (4*128*36 + 4*32*(128 + 8)) * 4;             // 143360
    cudaFuncSetAttribute(mma_gemm<112,1>, cudaFuncAttributeMaxDynamicSharedMemorySize, SM_M1);
    cudaFuncSetAttribute(mma_gemm<112,0>, cudaFuncAttributeMaxDynamicSharedMemorySize, SM_M0A);
    cudaFuncSetAttribute(mma_gemm<128,0>, cudaFuncAttributeMaxDynamicSharedMemorySize, SM_M0B);

    // 0) weight plane split (one-time cheap) + scan->conv kernel precompute
    wsplit_kernel<<<(512*336 + 255)/256, 256>>>(W_in,  wh + OFF_WIN,  wl + OFF_WIN,  512*336);
    wsplit_kernel<<<(336*1008 + 255)/256, 256>>>(W_qkv, wh + OFF_WQKV, wl + OFF_WQKV, 336*1008);
    wsplit_kernel<<<(336*512 + 255)/256, 256>>>(W_out, wh + OFF_WOUT, wl + OFF_WOUT, 336*512);
    prep_kernel<<<EE, 128>>>(A, Bp, Cp, conv_w);

    // 1) xp = dyt(x) @ W_in + b_in   [32768,512]x[512,336]  (MODE1: in-kernel DyT)
    mma_gemm<112,1><<<dim3(3, NN/128), 256, SM_M1>>>(x, nullptr, nullptr,
                                                     wh + OFF_WIN, wl + OFF_WIN,
                                                     b_in, xp, NN, EE, DIMC,
                                                     alpha, dyt_w, dyt_b);

    // 2) row-normalize -> pre-split xpn planes
    norm_kernel<<<NN/8, 256>>>(xp, xph, xpl);

    // 3) qkv = xpn @ W_qkv + b_qkv  [32768,336]x[336,1008]  (MODE0: no transform)
    mma_gemm<112,0><<<dim3(9, NN/128), 256, SM_M0A>>>(nullptr, xph, xpl,
                                                      wh + OFF_WQKV, wl + OFF_WQKV,
                                                      b_qkv, qkv, NN, E3, EE,
                                                      alpha, dyt_w, dyt_b);

    // 4) sparse attention (kh=1 -> argmax gather) + importance
    attn_kernel<<<NN/4, 128>>>(qkv, att, imp);

    // 5) exact sorted top-819 per batch
    topk_kernel<<<BB, 1024>>>(imp, idx);

    // 6) gather + combined dconv*scan causal convolution -> ys planes
    conv_kernel<<<dim3(EE/56, (KC + 63)/64, BB), 224>>>(att, idx, ysh, ysl);

    // 7) xproc = ys @ W_out + b_out  [6552,336]x[336,512]  (MODE0)
    mma_gemm<128,0><<<dim3(4, (BB*KC + 127)/128), 256, SM_M0B>>>(nullptr, ysh, ysl,
                                                                 wh + OFF_WOUT, wl + OFF_WOUT,
                                                                 b_out, xproc, BB*KC, DIMC, EE,
                                                                 alpha, dyt_w, dyt_b);

    // 8) out = residual
    residual_kernel<<<(NN*DIMC/4)/1024, 1024>>>((const float4*)x, (float4*)out);

    // 9) scatter selected rows
    scatter_kernel<<<BB*KC, 128>>>(x, xproc, idx, out);
}